// round 11
// baseline (speedup 1.0000x reference)
#include <cuda_runtime.h>
#include <cuda_bf16.h>
#include <cuda_fp8.h>
#include <cstdint>

#define U  2048
#define BB 16
#define D  32
#define LOG2E 1.4426950408889634f

// ---------------- device scratch (no allocations allowed) ----------------
__device__ float g_coldenom[3 * BB * U];
__device__ float g_O2[3 * BB * D];
__device__ float g_O1[3 * BB * D];
__device__ __align__(16) float g_CCA[BB * 2 * D];
__device__ unsigned g_ticket;
// bf16 hi rows (32 bf16 = 64B): 0=A*log2e 1=V 2=L 3=V*log2e
__device__ __align__(16) __nv_bfloat16 g_packh[4][BB * U * 32];
// e4m3 combo rows (64B): f1 variants (0,3) = [lo*512 | hi]; f2 (1,2) = [hi | lo*512]
__device__ __align__(16) uint8_t g_pack8[4][BB * U * 64];

// ---------------- helpers ----------------
__device__ __forceinline__ uint32_t smem_u32(const void* p) {
    uint32_t a;
    asm("{ .reg .u64 t; cvta.to.shared.u64 t, %1; cvt.u32.u64 %0, t; }" : "=r"(a) : "l"(p));
    return a;
}
__device__ __forceinline__ void ldsm4(uint32_t* r, uint32_t addr) {
    asm volatile("ldmatrix.sync.aligned.m8n8.x4.shared.b16 {%0,%1,%2,%3}, [%4];"
                 : "=r"(r[0]), "=r"(r[1]), "=r"(r[2]), "=r"(r[3]) : "r"(addr));
}
__device__ __forceinline__ void mma_bf16(float* c, const uint32_t* a,
                                         uint32_t b0, uint32_t b1) {
    asm volatile(
        "mma.sync.aligned.m16n8k16.row.col.f32.bf16.bf16.f32 "
        "{%0,%1,%2,%3}, {%4,%5,%6,%7}, {%8,%9}, {%0,%1,%2,%3};"
        : "+f"(c[0]), "+f"(c[1]), "+f"(c[2]), "+f"(c[3])
        : "r"(a[0]), "r"(a[1]), "r"(a[2]), "r"(a[3]), "r"(b0), "r"(b1));
}
__device__ __forceinline__ void mma_fp8(float* c, const uint32_t* a,
                                        uint32_t b0, uint32_t b1) {
    asm volatile(
        "mma.sync.aligned.m16n8k32.row.col.f32.e4m3.e4m3.f32 "
        "{%0,%1,%2,%3}, {%4,%5,%6,%7}, {%8,%9}, {%0,%1,%2,%3};"
        : "+f"(c[0]), "+f"(c[1]), "+f"(c[2]), "+f"(c[3])
        : "r"(a[0]), "r"(a[1]), "r"(a[2]), "r"(a[3]), "r"(b0), "r"(b1));
}
__device__ __forceinline__ float ex2(float x) {
    float y; asm("ex2.approx.f32 %0, %1;" : "=f"(y) : "f"(x)); return y;
}
__device__ __forceinline__ void cp16(uint32_t dst, const void* src) {
    asm volatile("cp.async.cg.shared.global [%0], [%1], 16;" :: "r"(dst), "l"(src));
}
#define CP_COMMIT() asm volatile("cp.async.commit_group;" ::: "memory")
#define CP_WAIT0()  asm volatile("cp.async.wait_group 0;" ::: "memory")
__device__ __forceinline__ uint8_t f2e4m3(float x) {
    __nv_fp8_e4m3 v(x);
    return *(uint8_t*)&v;
}

#define RSTB   80u            // SMEM row stride bytes (64B payload + 16 pad)
#define TILE_B (128u * RSTB)  // 10240 B per tile
#define S1H 0u
#define S18 10240u
#define S2H 20480u            // double-buffered
#define S28 40960u            // double-buffered
#define SMF 61440u
#define SMEM_TOTAL (SMF + (128 * 3 + 8 * 32) * 4)

// ---------------- K0: zero accumulators + ticket ----------------
__global__ void k_zero() {
    int i = blockIdx.x * blockDim.x + threadIdx.x;
    if (i < 3 * BB * U) g_coldenom[i] = 0.f;
    if (i < 3 * BB * D) { g_O2[i] = 0.f; g_O1[i] = 0.f; }
    if (i == 0) g_ticket = 0u;
}

// ---------------- Kp: pack fp32 -> bf16 hi + e4m3 combo ----------------
__global__ void k_pack(const float* __restrict__ A, const float* __restrict__ V,
                       const float* __restrict__ L) {
    int v = blockIdx.y;                               // 0:A*s 1:V 2:L 3:V*s
    const float* src = (v == 0) ? A : (v == 2 ? L : V);
    float scale = (v == 0 || v == 3) ? LOG2E : 1.f;
    int t = blockIdx.x * 256 + threadIdx.x;
    float x = src[t] * scale;
    __nv_bfloat16 hi = __float2bfloat16(x);
    float lo = (x - __bfloat162float(hi)) * 512.f;
    uint8_t h8 = f2e4m3(x), l8 = f2e4m3(lo);
    int row = t >> 5, k = t & 31;
    g_packh[v][(size_t)row * 32 + k] = hi;
    bool isF1 = (v == 0 || v == 3);
    g_pack8[v][(size_t)row * 64 + (isF1 ? k : 32 + k)] = l8;
    g_pack8[v][(size_t)row * 64 + (isF1 ? 32 + k : k)] = h8;
}

// ---------------- K1: persistent HMMA main pass ----------------
__global__ void __launch_bounds__(256, 2)
k_main(const float* __restrict__ A, const float* __restrict__ V,
       const float* __restrict__ L) {
    extern __shared__ char smem[];
    __shared__ unsigned s_tile;
    float* srow = (float*)(smem + SMF);               // [128]
    float* se0  = srow + 128;
    float* wbuf = se0 + 128;
    float (*red)[32] = (float (*)[32])(wbuf + 128);

    const int t = threadIdx.x;
    const int wid = t >> 5, lane = t & 31;
    const int warp_m = wid & 1;
    const int warp_n = wid >> 1;
    const uint32_t sb = smem_u32(smem);

    // per-lane ldmatrix address components
    const uint32_t ah_off = (uint32_t)(warp_m * 64 + (lane & 15)) * RSTB +
                            (uint32_t)(lane >> 4) * 16;
    const uint32_t bh_off = (uint32_t)(warp_n * 32 + ((lane >> 4) << 3) + (lane & 7)) * RSTB +
                            (uint32_t)((lane >> 3) & 1) * 16;
    const uint32_t a8_off = (uint32_t)(warp_m * 64 + ((lane >> 3) & 1) * 8 + (lane & 7)) * RSTB +
                            (uint32_t)(lane >> 4) * 16;
    const uint32_t b8_off = (uint32_t)(warp_n * 32 + (lane >> 3) * 8 + (lane & 7)) * RSTB;

    while (true) {
        if (t == 0) s_tile = atomicAdd(&g_ticket, 1u);
        __syncthreads();
        unsigned tile = s_tile;
        if (tile >= 768u) break;
        const int p = tile >> 8;                      // /256
        const int rem = tile & 255;
        const int b = rem >> 4, tileI = rem & 15;

        const int v1 = (p == 2) ? 3 : 0;              // f1 (log2e-scaled): A,A,V
        const int v2 = (p == 0) ? 1 : 2;              // f2: V,L,L
        const __nv_bfloat16* F1h = &g_packh[v1][(size_t)(b * U + tileI * 128) * 32];
        const uint8_t*      F18 = &g_pack8[v1][(size_t)(b * U + tileI * 128) * 64];
        const __nv_bfloat16* F2h = &g_packh[v2][(size_t)b * U * 32];
        const uint8_t*      F28 = &g_pack8[v2][(size_t)b * U * 64];
        const float* F1f = ((p == 2) ? V : A) + (size_t)(b * U + tileI * 128) * D;

        if (t < 128) { srow[t] = 0.f; se0[t] = 0.f; }

        // prologue: f1 tiles + first f2 tiles (each 512 uint4)
#pragma unroll
        for (int q = 0; q < 2; q++) {
            int lin = q * 256 + t;
            uint32_t so = (uint32_t)(lin >> 2) * RSTB + (uint32_t)(lin & 3) * 16;
            cp16(sb + S1H + so, (const uint4*)F1h + lin);
            cp16(sb + S18 + so, (const uint4*)F18 + lin);
            cp16(sb + S2H + so, (const uint4*)F2h + lin);
            cp16(sb + S28 + so, (const uint4*)F28 + lin);
        }
        CP_COMMIT();
        CP_WAIT0();
        __syncthreads();

        float rowsum = 0.f, e0 = 0.f;
        const int cdbase = (p * BB + b) * U;

        for (int jt = 0; jt < 16; ++jt) {
            const uint32_t cur = (uint32_t)(jt & 1) * TILE_B;
            const uint32_t nxt = TILE_B - cur;
            if (jt + 1 < 16) {                        // prefetch next j-tiles
                const uint4* sh = (const uint4*)(F2h + (size_t)(jt + 1) * 128 * 32);
                const uint4* s8 = (const uint4*)(F28 + (size_t)(jt + 1) * 128 * 64);
#pragma unroll
                for (int q = 0; q < 2; q++) {
                    int lin = q * 256 + t;
                    uint32_t so = (uint32_t)(lin >> 2) * RSTB + (uint32_t)(lin & 3) * 16;
                    cp16(sb + S2H + nxt + so, sh + lin);
                    cp16(sb + S28 + nxt + so, s8 + lin);
                }
                CP_COMMIT();
            }

            float acc[4][4][4];
#pragma unroll
            for (int ma = 0; ma < 4; ma++)
#pragma unroll
                for (int na = 0; na < 4; na++)
#pragma unroll
                    for (int k = 0; k < 4; k++) acc[ma][na][k] = 0.f;

            // ---- fp8 cross terms: K=64 as 2 x m16n8k32 ----
#pragma unroll
            for (int ch = 0; ch < 2; ch++) {
                const uint32_t chb = (uint32_t)ch * 32;
                uint32_t af[4][4];
#pragma unroll
                for (int ma = 0; ma < 4; ma++)
                    ldsm4(af[ma], sb + S18 + a8_off + (uint32_t)ma * 16 * RSTB + chb);
                uint32_t b0[4], b1[4];
                ldsm4(b0, sb + S28 + cur + b8_off + chb);
                ldsm4(b1, sb + S28 + cur + b8_off + chb + 16);
#pragma unroll
                for (int ma = 0; ma < 4; ma++)
#pragma unroll
                    for (int na = 0; na < 4; na++)
                        mma_fp8(acc[ma][na], af[ma], b0[na], b1[na]);
            }
            // scale cross terms back by 2^-9
#pragma unroll
            for (int ma = 0; ma < 4; ma++)
#pragma unroll
                for (int na = 0; na < 4; na++)
#pragma unroll
                    for (int k = 0; k < 4; k++) acc[ma][na][k] *= 0.001953125f;

            // ---- bf16 hi*hi: K=32 as 2 x m16n8k16 ----
#pragma unroll
            for (int s = 0; s < 2; s++) {
                const uint32_t sby = (uint32_t)s * 32;
                uint32_t af[4][4];
#pragma unroll
                for (int ma = 0; ma < 4; ma++)
                    ldsm4(af[ma], sb + S1H + ah_off + (uint32_t)ma * 16 * RSTB + sby);
                uint32_t bf[2][4];
#pragma unroll
                for (int q = 0; q < 2; q++)
                    ldsm4(bf[q], sb + S2H + cur + bh_off + (uint32_t)q * 16 * RSTB + sby);
#pragma unroll
                for (int ma = 0; ma < 4; ma++)
#pragma unroll
                    for (int na = 0; na < 4; na++)
                        mma_bf16(acc[ma][na], af[ma],
                                 bf[na >> 1][(na & 1) * 2], bf[na >> 1][(na & 1) * 2 + 1]);
            }

            // ---- epilogue: exp2 + row/col reductions ----
            float colp[4][2];
#pragma unroll
            for (int na = 0; na < 4; na++) { colp[na][0] = 0.f; colp[na][1] = 0.f; }

#pragma unroll
            for (int ma = 0; ma < 4; ma++) {
                float rp0 = 0.f, rp1 = 0.f;
#pragma unroll
                for (int na = 0; na < 4; na++) {
                    float v0 = ex2(acc[ma][na][0]);
                    float v1 = ex2(acc[ma][na][1]);
                    float v2 = ex2(acc[ma][na][2]);
                    float v3 = ex2(acc[ma][na][3]);
                    rp0 += v0 + v1;  rp1 += v2 + v3;
                    colp[na][0] += v0 + v2;  colp[na][1] += v1 + v3;
                    if (jt == 0 && warp_n == 0 && na == 0 && (lane & 3) == 0) {
                        int r0 = warp_m * 64 + ma * 16 + (lane >> 2);
                        se0[r0]     = v0;
                        se0[r0 + 8] = v2;
                    }
                }
                rp0 += __shfl_xor_sync(0xffffffffu, rp0, 1);
                rp0 += __shfl_xor_sync(0xffffffffu, rp0, 2);
                rp1 += __shfl_xor_sync(0xffffffffu, rp1, 1);
                rp1 += __shfl_xor_sync(0xffffffffu, rp1, 2);
                if ((lane & 3) == 0) {
                    int r0 = warp_m * 64 + ma * 16 + (lane >> 2);
                    atomicAdd(&srow[r0], rp0);
                    atomicAdd(&srow[r0 + 8], rp1);
                }
            }
#pragma unroll
            for (int na = 0; na < 4; na++) {
#pragma unroll
                for (int par = 0; par < 2; par++) {
                    float c = colp[na][par];
                    c += __shfl_xor_sync(0xffffffffu, c, 4);
                    c += __shfl_xor_sync(0xffffffffu, c, 8);
                    c += __shfl_xor_sync(0xffffffffu, c, 16);
                    if ((lane >> 2) == 0)
                        atomicAdd(&g_coldenom[cdbase + jt * 128 + warp_n * 32 +
                                              na * 8 + 2 * lane + par], c);
                }
            }

            CP_WAIT0();
            __syncthreads();
        }

        if (t < 128) wbuf[t] = se0[t] / srow[t];
        __syncthreads();

        // O2 partial: Σ_i w_i * f1[i][d]  (original fp32 rows, L2-resident)
        {
            int d = t & 31, chk = t >> 5;
            float po = 0.f;
#pragma unroll
            for (int ii = 0; ii < 16; ii++) {
                int i = chk * 16 + ii;
                po += wbuf[i] * F1f[(size_t)i * D + d];
            }
            red[chk][d] = po;
        }
        __syncthreads();
        if (t < 32) {
            float s = 0.f;
#pragma unroll
            for (int c = 0; c < 8; c++) s += red[c][t];
            atomicAdd(&g_O2[(p * BB + b) * D + t], s);
        }
        __syncthreads();
    }
}

// ---------------- K2: O1 partial sums (split 8x over j) ----------------
__global__ void k_stage2(const float* __restrict__ A, const float* __restrict__ V,
                         const float* __restrict__ L) {
    const int p = blockIdx.x, b = blockIdx.y, z = blockIdx.z;
    const float* f1 = (p == 2 ? V : A) + (size_t)b * U * D;
    const float* f2 = (p == 0 ? V : L) + (size_t)b * U * D;
    const int t = threadIdx.x;
    __shared__ float sF10[32];
    __shared__ float sAcc[256][33];
    __shared__ float red[8][32];

    if (t < 32) sF10[t] = f1[t];
    __syncthreads();

    int j = z * 256 + t;
    float f[32];
    const float4* rowp = (const float4*)(f2 + (size_t)j * D);
#pragma unroll
    for (int q = 0; q < 8; q++) *(float4*)&f[q * 4] = rowp[q];
    float dot = 0.f;
#pragma unroll
    for (int k = 0; k < 32; k++) dot += f[k] * sF10[k];
    float w = __expf(dot) / g_coldenom[(p * BB + b) * U + j];
#pragma unroll
    for (int d = 0; d < 32; d++) sAcc[t][d] = w * f[d];
    __syncthreads();
    {
        int d = t & 31, g = t >> 5;
        float s = 0.f;
#pragma unroll
        for (int m = 0; m < 32; m++) s += sAcc[g * 32 + m][d];
        red[g][d] = s;
    }
    __syncthreads();
    if (t < 32) {
        float o1 = 0.f;
#pragma unroll
        for (int g = 0; g < 8; g++) o1 += red[g][t];
        atomicAdd(&g_O1[(p * BB + b) * D + t], o1);
    }
}

// ---------------- K3: Bi assembly + FC head + batch softmax + CCA ----------
__device__ __forceinline__ float fast_tanh(float x) {
    float y;
    asm("tanh.approx.f32 %0, %1;" : "=f"(y) : "f"(x));
    return y;
}

__global__ void k_head(const float* __restrict__ W1, const float* __restrict__ B1,
                       const float* __restrict__ W2, const float* __restrict__ A,
                       const float* __restrict__ V, const float* __restrict__ L) {
    __shared__ float sW1[64 * 65];
    __shared__ float sBi[48 * 64];
    __shared__ float sB1[64], sW2[64];
    __shared__ float sCi[48];
    __shared__ float sMax[3], sSum[3];
    const int t = threadIdx.x, lane = t & 31, w = t >> 5;

    for (int i = t; i < 4096; i += 256) {
        int h = i >> 6, d = i & 63;
        sW1[d * 65 + h] = W1[i];
    }
    for (int i = t; i < 1536; i += 256) {
        int row = i >> 5, d = i & 31;
        int b = row / 3, p = row - b * 3;
        const float* f1 = (p == 2 ? V : A) + (size_t)b * U * D;
        const float* f2 = (p == 0 ? V : L) + (size_t)b * U * D;
        int pb = (p * BB + b) * D;
        sBi[row * 64 + d]      = g_O1[pb + d] * f1[d];
        sBi[row * 64 + 32 + d] = g_O2[pb + d] * f2[d];
    }
    if (t < 64) { sB1[t] = B1[t]; sW2[t] = W2[t]; }
    __syncthreads();

    for (int rr = 0; rr < 6; rr++) {
        int row = rr * 8 + w;
        float c = 0.f;
#pragma unroll
        for (int hh = 0; hh < 2; hh++) {
            int hid = hh * 32 + lane;
            const float* bi = &sBi[row * 64];
            float a0 = sB1[hid], a1 = 0.f, a2 = 0.f, a3 = 0.f;
#pragma unroll
            for (int dd = 0; dd < 64; dd += 4) {
                a0 += sW1[(dd + 0) * 65 + hid] * bi[dd + 0];
                a1 += sW1[(dd + 1) * 65 + hid] * bi[dd + 1];
                a2 += sW1[(dd + 2) * 65 + hid] * bi[dd + 2];
                a3 += sW1[(dd + 3) * 65 + hid] * bi[dd + 3];
            }
            c += fast_tanh((a0 + a1) + (a2 + a3)) * sW2[hid];
        }
#pragma unroll
        for (int o = 16; o; o >>= 1) c += __shfl_xor_sync(0xffffffffu, c, o);
        if (lane == 0) sCi[row] = c;
    }
    __syncthreads();
    if (t < 3) {
        float m = -1e30f;
        for (int b = 0; b < BB; b++) m = fmaxf(m, sCi[b * 3 + t]);
        float s = 0.f;
        for (int b = 0; b < BB; b++) s += __expf(sCi[b * 3 + t] - m);
        sMax[t] = m; sSum[t] = s;
    }
    __syncthreads();
    for (int it = 0; it < 4; it++) {
        int idx = it * 256 + t;
        int b = idx >> 6, dd = idx & 63;
        float o = 0.f;
#pragma unroll
        for (int k = 0; k < 3; k++) {
            float al = __expf(sCi[b * 3 + k] - sMax[k]) / sSum[k];
            o += al * sBi[(b * 3 + k) * 64 + dd];
        }
        g_CCA[idx] = o;
    }
}

// ---------------- K4: broadcast CCA_i across U ----------------
__global__ void k_bcast(float4* __restrict__ out) {
    int g = blockIdx.x * 256 + threadIdx.x;
    int b = g >> 15;
    int d4 = g & 15;
    out[g] = *(const float4*)&g_CCA[(b * 16 + d4) * 4];
}

// ---------------- launcher ----------------
extern "C" void kernel_launch(void* const* d_in, const int* in_sizes, int n_in,
                              void* d_out, int out_size) {
    (void)in_sizes; (void)n_in; (void)out_size;
    const float* A  = (const float*)d_in[0];
    const float* V  = (const float*)d_in[1];
    const float* L  = (const float*)d_in[2];
    const float* W1 = (const float*)d_in[3];
    const float* B1 = (const float*)d_in[4];
    const float* W2 = (const float*)d_in[5];

    static int smem_set = 0;
    if (!smem_set) {
        cudaFuncSetAttribute(k_main, cudaFuncAttributeMaxDynamicSharedMemorySize,
                             SMEM_TOTAL);
        smem_set = 1;
    }

    k_zero<<<384, 256>>>();
    k_pack<<<dim3(4096, 4), 256>>>(A, V, L);
    k_main<<<296, 256, SMEM_TOTAL>>>(A, V, L);
    k_stage2<<<dim3(3, 16, 8), 256>>>(A, V, L);
    k_head<<<1, 256>>>(W1, B1, W2, A, V, L);
    k_bcast<<<2048, 256>>>((float4*)d_out);
}